// round 12
// baseline (speedup 1.0000x reference)
#include <cuda_runtime.h>
#include <cuda_bf16.h>

// GeometricHyperConnections — fused, HBM-bound.
// b=4, s=4, T=2048, d=2048, k=4.
// One CTA per 4 consecutive tokens; 512 threads (one float4 column each).
// Software-pipelined: Sinkhorn(i+1) (scalar, warp-0 lane-0) runs concurrently
// with token i's output stores. ONE barrier per token. The r tile in SMEM is
// thread-private (each thread touches only its own column) so it needs no
// barrier protection; red and Hs are double-buffered.

#define T_DIM 2048
#define D_DIM 2048
#define D4    512         // D_DIM/4
#define B_DIM 4
#define S_DIM 4
#define K_DIM 4
#define TPC   4           // tokens per CTA
#define NWARP 16
#define TAU   0.05f
#define RMSEPS 1e-6f

// dynamic SMEM layout (float4 units)
#define WP_OFF   0
#define TILE_OFF (K_DIM * D4)                   // 2048
#define AUX_OFF  (TILE_OFF + 2 * S_DIM * D4)    // 6144
// aux floats: red[2][16][20]=640, coords 16, Hs[2][16]=32  -> 688 = 172 f4
#define SMEM_F4    (AUX_OFF + 172)
#define SMEM_BYTES (SMEM_F4 * 16)

__global__ void __launch_bounds__(512, 2)
ghc_kernel(const float* __restrict__ resid,
           const float* __restrict__ branch,
           const float* __restrict__ rmsw,
           const float* __restrict__ projW,
           const float* __restrict__ log_sigma,
           const float* __restrict__ pre_logits,
           const float* __restrict__ post_logits,
           float* __restrict__ out_bi,     // (B,T,D)
           float* __restrict__ out_mix)    // (B*S,T,D)
{
    extern __shared__ float4 sm[];
    float4* wp4  = sm + WP_OFF;                 // [K_DIM][D4]
    float4* tile = sm + TILE_OFF;               // [2][S_DIM][D4]
    float*  red    = (float*)(sm + AUX_OFF);    // [2][NWARP][20]
    float*  coords = red + 2 * NWARP * 20;      // [16]
    float*  Hsb    = coords + 16;               // [2][16]

    const int tid  = threadIdx.x;
    const int warp = tid >> 5, lane = tid & 31;
    const int blk  = blockIdx.x;
    const int bi   = blk >> 9;
    const int t0   = (blk & 511) * TPC;

    const float4* R4  = (const float4*)resid;
    const float4* W4  = (const float4*)rmsw;
    const float4* P4  = (const float4*)projW;
    const float4* BO4 = (const float4*)branch;
    float4* OBI = (float4*)out_bi;
    float4* OMX = (float4*)out_mix;

    // ---- fused w*proj column (thread-private in SMEM; no barrier needed) --
    {
        const float4 w = W4[tid];
#pragma unroll
        for (int k = 0; k < K_DIM; k++) {
            const float4 p = P4[k * D4 + tid];
            wp4[k * D4 + tid] = make_float4(w.x*p.x, w.y*p.y, w.z*p.z, w.w*p.w);
        }
    }

    // ---- Hpre / Hpost -----------------------------------------------------
    float hp[4], hq[4];
    {
        float l[4], mx, sm_;
#pragma unroll
        for (int i = 0; i < 4; i++) l[i] = __ldg(&pre_logits[i]);
        mx = fmaxf(fmaxf(l[0], l[1]), fmaxf(l[2], l[3]));
        sm_ = 0.f;
#pragma unroll
        for (int i = 0; i < 4; i++) { hp[i] = __expf(l[i] - mx); sm_ += hp[i]; }
        sm_ = 1.f / sm_;
#pragma unroll
        for (int i = 0; i < 4; i++) hp[i] *= sm_;
#pragma unroll
        for (int i = 0; i < 4; i++) l[i] = __ldg(&post_logits[i]);
        mx = fmaxf(fmaxf(l[0], l[1]), fmaxf(l[2], l[3]));
        sm_ = 0.f;
#pragma unroll
        for (int i = 0; i < 4; i++) { hq[i] = __expf(l[i] - mx); sm_ += hq[i]; }
        sm_ = 1.f / sm_;
#pragma unroll
        for (int i = 0; i < 4; i++) hq[i] *= sm_;
    }

    unsigned rb[S_DIM];
#pragma unroll
    for (int s = 0; s < S_DIM; s++)
        rb[s] = (unsigned)((bi * S_DIM + s) * T_DIM + t0) * D4 + tid;
    unsigned bb = (unsigned)(bi * T_DIM + t0) * D4 + tid;

    // ================= stats macro-ish lambda ==============================
    auto do_stats = [&](float4* rr, int buf) {
        float acc[20];
#pragma unroll
        for (int s = 0; s < S_DIM; s++)
            acc[s] = rr[s].x*rr[s].x + rr[s].y*rr[s].y
                   + rr[s].z*rr[s].z + rr[s].w*rr[s].w;
#pragma unroll
        for (int k = 0; k < K_DIM; k++) {
            const float4 wk = wp4[k * D4 + tid];
#pragma unroll
            for (int s = 0; s < S_DIM; s++)
                acc[4 + s*4 + k] = rr[s].x*wk.x + rr[s].y*wk.y
                                 + rr[s].z*wk.z + rr[s].w*wk.w;
        }
#pragma unroll
        for (int s = 0; s < S_DIM; s++)
            tile[buf * (S_DIM * D4) + s * D4 + tid] = rr[s];
#pragma unroll
        for (int v = 0; v < 20; v++) {
            float x = acc[v];
#pragma unroll
            for (int off = 16; off; off >>= 1)
                x += __shfl_xor_sync(0xffffffffu, x, off);
            acc[v] = x;
        }
        if (lane == 0) {
#pragma unroll
            for (int v = 0; v < 20; v++)
                red[buf * (NWARP * 20) + warp * 20 + v] = acc[v];
        }
    };

    auto do_sinkhorn = [&](int buf) {   // warp 0 only
        const float* rd = red + buf * (NWARP * 20);
        if (lane < 16) {
            const int si = lane >> 2;
            float ssq = 0.f, dsum = 0.f;
#pragma unroll
            for (int w = 0; w < NWARP; w++) {
                ssq  += rd[w * 20 + si];
                dsum += rd[w * 20 + 4 + lane];
            }
            const float scale = rsqrtf(ssq * (1.f / (float)D_DIM) + RMSEPS);
            coords[lane] = scale * dsum;
        }
        __syncwarp();
        if (lane == 0) {
            const float inv = __expf(-2.f * __ldg(log_sigma)) * (0.5f / TAU);
            float C[16];
#pragma unroll
            for (int x = 0; x < 16; x++) C[x] = coords[x];
            float K[16];
#pragma unroll
            for (int ii = 0; ii < 4; ii++)
#pragma unroll
                for (int jj = 0; jj < 4; jj++) {
                    float ds = 0.f;
#pragma unroll
                    for (int k = 0; k < 4; k++) {
                        const float df = C[ii*4 + k] - C[jj*4 + k];
                        ds += df * df;
                    }
                    K[ii*4 + jj] = __expf(-ds * inv);
                }
            float a[4], b[4] = {1.f, 1.f, 1.f, 1.f};
#pragma unroll
            for (int it = 0; it < 10; it++) {
#pragma unroll
                for (int ii = 0; ii < 4; ii++) {
                    const float d = K[ii*4+0]*b[0] + K[ii*4+1]*b[1]
                                  + K[ii*4+2]*b[2] + K[ii*4+3]*b[3];
                    a[ii] = __fdividef(0.25f, d);
                }
#pragma unroll
                for (int jj = 0; jj < 4; jj++) {
                    const float d = K[0*4+jj]*a[0] + K[1*4+jj]*a[1]
                                  + K[2*4+jj]*a[2] + K[3*4+jj]*a[3];
                    b[jj] = __fdividef(0.25f, d);
                }
            }
            float* H = Hsb + buf * 16;
#pragma unroll
            for (int ii = 0; ii < 4; ii++)
#pragma unroll
                for (int jj = 0; jj < 4; jj++)
                    H[ii*4 + jj] = 4.f * K[ii*4 + jj] * a[ii] * b[jj];
        }
    };

    // ================= prologue: token 0 ===================================
    float4 rr[S_DIM];
#pragma unroll
    for (int s = 0; s < S_DIM; s++) rr[s] = __ldcs(&R4[rb[s]]);
    float4 bo = __ldcs(&BO4[bb]);

    do_stats(rr, 0);
    // issue r(1) while Sinkhorn(0) runs
#pragma unroll
    for (int s = 0; s < S_DIM; s++) rr[s] = __ldcs(&R4[rb[s] + D4]);

    __syncthreads();                 // red[0] complete
    if (warp == 0) do_sinkhorn(0);   // -> Hsb[0]

    // ================= token loop ==========================================
#pragma unroll
    for (int i = 0; i < TPC; i++) {
        const int cb = i & 1;

        if (i + 1 < TPC) do_stats(rr, (i + 1) & 1);

        __syncthreads();             // gates red[(i+1)&1] AND Hs[cb] from warp0

        if (warp == 0 && i + 1 < TPC) do_sinkhorn((i + 1) & 1);

        float4 bon;
        if (i + 1 < TPC) bon = __ldcs(&BO4[bb + D4]);
        if (i + 2 < TPC) {
#pragma unroll
            for (int s = 0; s < S_DIM; s++) rr[s] = __ldcs(&R4[rb[s] + 2 * D4]);
        }

        // ---- stores for token i (overlap warp0's Sinkhorn) ----------------
        const float4 ra = tile[cb * (S_DIM*D4) + 0*D4 + tid];
        const float4 rbv= tile[cb * (S_DIM*D4) + 1*D4 + tid];
        const float4 rcv= tile[cb * (S_DIM*D4) + 2*D4 + tid];
        const float4 rdv= tile[cb * (S_DIM*D4) + 3*D4 + tid];
        {
            float4 o;
            o.x = hp[0]*ra.x + hp[1]*rbv.x + hp[2]*rcv.x + hp[3]*rdv.x;
            o.y = hp[0]*ra.y + hp[1]*rbv.y + hp[2]*rcv.y + hp[3]*rdv.y;
            o.z = hp[0]*ra.z + hp[1]*rbv.z + hp[2]*rcv.z + hp[3]*rdv.z;
            o.w = hp[0]*ra.w + hp[1]*rbv.w + hp[2]*rcv.w + hp[3]*rdv.w;
            __stcs(&OBI[bb], o);
        }
        const float* H = Hsb + cb * 16;
#pragma unroll
        for (int u = 0; u < 4; u++) {
            const float h0 = H[0*4 + u], h1 = H[1*4 + u],
                        h2 = H[2*4 + u], h3 = H[3*4 + u], hb = hq[u];
            float4 q;
            q.x = hb*bo.x + h0*ra.x + h1*rbv.x + h2*rcv.x + h3*rdv.x;
            q.y = hb*bo.y + h0*ra.y + h1*rbv.y + h2*rcv.y + h3*rdv.y;
            q.z = hb*bo.z + h0*ra.z + h1*rbv.z + h2*rcv.z + h3*rdv.z;
            q.w = hb*bo.w + h0*ra.w + h1*rbv.w + h2*rcv.w + h3*rdv.w;
            __stcs(&OMX[rb[u]], q);
        }

        if (i + 1 < TPC) {
            bo = bon;
#pragma unroll
            for (int s = 0; s < S_DIM; s++) rb[s] += D4;
            bb += D4;
        }
    }
}

extern "C" void kernel_launch(void* const* d_in, const int* in_sizes, int n_in,
                              void* d_out, int out_size)
{
    const float* resid       = (const float*)d_in[0];
    const float* branch      = (const float*)d_in[1];
    const float* rmsw        = (const float*)d_in[2];
    const float* projW       = (const float*)d_in[3];
    const float* log_sigma   = (const float*)d_in[4];
    const float* pre_logits  = (const float*)d_in[5];
    const float* post_logits = (const float*)d_in[6];

    float* out_bi  = (float*)d_out;                                   // (B,T,D) first
    float* out_mix = (float*)d_out + (size_t)B_DIM * T_DIM * D_DIM;   // then (B*S,T,D)

    cudaFuncSetAttribute(ghc_kernel,
                         cudaFuncAttributeMaxDynamicSharedMemorySize, SMEM_BYTES);

    dim3 grid(B_DIM * T_DIM / TPC);   // 2048 CTAs x 4 tokens
    dim3 block(512);
    ghc_kernel<<<grid, block, SMEM_BYTES>>>(resid, branch, rmsw, projW, log_sigma,
                                            pre_logits, post_logits, out_bi, out_mix);
}

// round 13
// speedup vs baseline: 1.1980x; 1.1980x over previous
#include <cuda_runtime.h>
#include <cuda_bf16.h>

// GeometricHyperConnections — fused, HBM-bound.
// b=4, s=4, T=2048, d=2048, k=4.
// R5 champion frame: one CTA per token, 256 threads, 4 CTAs/SM, SMEM staging,
// ONE block barrier, per-warp redundant Sinkhorn.
// R13 change: Sinkhorn is the SCALAR multiplicative form in lane 0 of each
// warp (K diagonal = 1 makes log-domain max-subtraction unnecessary) —
// ~900 cyc of FMA/ILP instead of ~3000 cyc of 80 dependent shuffles.

#define T_DIM 2048
#define D_DIM 2048
#define D4    512         // D_DIM/4
#define B_DIM 4
#define S_DIM 4
#define K_DIM 4
#define TAU   0.05f
#define RMSEPS 1e-6f

__global__ void __launch_bounds__(256, 4)
ghc_kernel(const float* __restrict__ resid,
           const float* __restrict__ branch,
           const float* __restrict__ rmsw,
           const float* __restrict__ projW,
           const float* __restrict__ log_sigma,
           const float* __restrict__ pre_logits,
           const float* __restrict__ post_logits,
           float* __restrict__ out_bi,     // (B,T,D)
           float* __restrict__ out_mix)    // (B*S,T,D)
{
    __shared__ float tile[S_DIM][D_DIM];   // staged residual rows (32 KB)
    __shared__ float red[8][5];            // per-warp partials
    __shared__ float coords_w[8][16];      // per-warp coords
    __shared__ float Hs_w[8][16];          // per-warp H result

    const int tid  = threadIdx.x;
    const int warp = tid >> 5, lane = tid & 31;
    const int m    = blockIdx.x;
    const int bi   = m >> 11;              // m / T_DIM
    const int t    = m & (T_DIM - 1);

    const float4* R4  = (const float4*)resid;
    const float4* W4  = (const float4*)rmsw;
    const float4* P4  = (const float4*)projW;
    const float4* BO4 = (const float4*)branch;

    size_t rbase[S_DIM];
#pragma unroll
    for (int si = 0; si < S_DIM; si++)
        rbase[si] = ((size_t)(bi * S_DIM + si) * T_DIM + t) * D4;
    const size_t bbase = ((size_t)bi * T_DIM + t) * D4;

    // ---- Hpre / Hpost: every thread computes both tiny softmaxes ----------
    float hp[4], hq[4];
    {
        float l[4], mx, sm;
#pragma unroll
        for (int i = 0; i < 4; i++) l[i] = __ldg(&pre_logits[i]);
        mx = fmaxf(fmaxf(l[0], l[1]), fmaxf(l[2], l[3]));
        sm = 0.f;
#pragma unroll
        for (int i = 0; i < 4; i++) { hp[i] = __expf(l[i] - mx); sm += hp[i]; }
        sm = 1.f / sm;
#pragma unroll
        for (int i = 0; i < 4; i++) hp[i] *= sm;
#pragma unroll
        for (int i = 0; i < 4; i++) l[i] = __ldg(&post_logits[i]);
        mx = fmaxf(fmaxf(l[0], l[1]), fmaxf(l[2], l[3]));
        sm = 0.f;
#pragma unroll
        for (int i = 0; i < 4; i++) { hq[i] = __expf(l[i] - mx); sm += hq[i]; }
        sm = 1.f / sm;
#pragma unroll
        for (int i = 0; i < 4; i++) hq[i] *= sm;
    }

    // ---------------- Pass 1: stream-split stats + SMEM staging -----------
    {
        const int s = tid >> 6;            // stream owned by this thread
        const int g = tid & 63;            // lane within stream group
        const size_t rb = rbase[s];
        float4* tl4 = (float4*)tile[s];

        float ssq = 0.f, d0 = 0.f, d1 = 0.f, d2 = 0.f, d3 = 0.f;
#pragma unroll
        for (int i = 0; i < 8; i++) {
            const int c = g + 64 * i;
            const float4 r = __ldcs(&R4[rb + c]);
            tl4[c] = r;
            const float4 w  = W4[c];
            const float4 p0 = P4[0 * D4 + c];
            const float4 p1 = P4[1 * D4 + c];
            const float4 p2 = P4[2 * D4 + c];
            const float4 p3 = P4[3 * D4 + c];
            ssq += r.x*r.x + r.y*r.y + r.z*r.z + r.w*r.w;
            const float ax = r.x*w.x, ay = r.y*w.y, az = r.z*w.z, aw = r.w*w.w;
            d0 += ax*p0.x + ay*p0.y + az*p0.z + aw*p0.w;
            d1 += ax*p1.x + ay*p1.y + az*p1.z + aw*p1.w;
            d2 += ax*p2.x + ay*p2.y + az*p2.z + aw*p2.w;
            d3 += ax*p3.x + ay*p3.y + az*p3.z + aw*p3.w;
        }

        float vals[5] = {ssq, d0, d1, d2, d3};
#pragma unroll
        for (int v = 0; v < 5; v++) {
            float x = vals[v];
#pragma unroll
            for (int off = 16; off; off >>= 1)
                x += __shfl_xor_sync(0xffffffffu, x, off);
            vals[v] = x;
        }
        if (lane == 0) {
#pragma unroll
            for (int v = 0; v < 5; v++) red[warp][v] = vals[v];
        }
    }

    // Prefetch branch_output while partials settle (overlaps barrier).
    const float4 bo0 = __ldcs(&BO4[bbase + tid]);
    const float4 bo1 = __ldcs(&BO4[bbase + tid + 256]);

    __syncthreads();   // the ONLY block barrier

    float4* OBI = (float4*)out_bi;
    float4* OMX = (float4*)out_mix;

    // ---- branch_input first: only needs Hpre; stores drain during Sinkhorn
#pragma unroll
    for (int j = 0; j < 2; j++) {
        const int c = tid + j * 256;
        const float4 r0 = ((const float4*)tile[0])[c];
        const float4 r1 = ((const float4*)tile[1])[c];
        const float4 r2 = ((const float4*)tile[2])[c];
        const float4 r3 = ((const float4*)tile[3])[c];
        float4 o;
        o.x = hp[0]*r0.x + hp[1]*r1.x + hp[2]*r2.x + hp[3]*r3.x;
        o.y = hp[0]*r0.y + hp[1]*r1.y + hp[2]*r2.y + hp[3]*r3.y;
        o.z = hp[0]*r0.z + hp[1]*r1.z + hp[2]*r2.z + hp[3]*r3.z;
        o.w = hp[0]*r0.w + hp[1]*r1.w + hp[2]*r2.w + hp[3]*r3.w;
        __stcs(&OBI[bbase + c], o);
    }

    // ---- Every warp: coords (lanes 0-15), then SCALAR Sinkhorn in lane 0 --
    if (lane < 16) {
        // lane = si*4 + k ; group si spans warps 2si, 2si+1
        const int si = lane >> 2, k = lane & 3;
        const float dsum = red[2 * si][1 + k] + red[2 * si + 1][1 + k];
        const float ssq  = red[2 * si][0]     + red[2 * si + 1][0];
        const float scale = rsqrtf(ssq * (1.f / (float)D_DIM) + RMSEPS);
        coords_w[warp][lane] = scale * dsum;
    }
    __syncwarp();
    if (lane == 0) {
        // Z_ij = -dist_sq/(2*sigma^2*tau); K = exp(Z); diagonal = 1 -> safe
        const float inv = __expf(-2.f * __ldg(log_sigma)) * (0.5f / TAU);
        float C[16];
#pragma unroll
        for (int x = 0; x < 16; x++) C[x] = coords_w[warp][x];
        float K[16];
#pragma unroll
        for (int ii = 0; ii < 4; ii++)
#pragma unroll
            for (int jj = 0; jj < 4; jj++) {
                float ds = 0.f;
#pragma unroll
                for (int k = 0; k < 4; k++) {
                    const float df = C[ii*4 + k] - C[jj*4 + k];
                    ds += df * df;
                }
                K[ii*4 + jj] = __expf(-ds * inv);
            }
        // multiplicative Sinkhorn: a = 1/4 / (K b); b = 1/4 / (K^T a)
        float a[4], b[4] = {1.f, 1.f, 1.f, 1.f};
#pragma unroll
        for (int it = 0; it < 10; it++) {
#pragma unroll
            for (int ii = 0; ii < 4; ii++) {
                const float d = K[ii*4+0]*b[0] + K[ii*4+1]*b[1]
                              + K[ii*4+2]*b[2] + K[ii*4+3]*b[3];
                a[ii] = __fdividef(0.25f, d);
            }
#pragma unroll
            for (int jj = 0; jj < 4; jj++) {
                const float d = K[0*4+jj]*a[0] + K[1*4+jj]*a[1]
                              + K[2*4+jj]*a[2] + K[3*4+jj]*a[3];
                b[jj] = __fdividef(0.25f, d);
            }
        }
#pragma unroll
        for (int ii = 0; ii < 4; ii++)
#pragma unroll
            for (int jj = 0; jj < 4; jj++)
                Hs_w[warp][ii*4 + jj] = 4.f * K[ii*4 + jj] * a[ii] * b[jj];
    }
    __syncwarp();

    // ---------------- Mixed outputs ----------------------------------------
    const float* H = Hs_w[warp];
#pragma unroll
    for (int j = 0; j < 2; j++) {
        const int c = tid + j * 256;
        const float4 r0 = ((const float4*)tile[0])[c];
        const float4 r1 = ((const float4*)tile[1])[c];
        const float4 r2 = ((const float4*)tile[2])[c];
        const float4 r3 = ((const float4*)tile[3])[c];
        const float4 bo = (j == 0) ? bo0 : bo1;

#pragma unroll
        for (int u = 0; u < 4; u++) {
            const float h0 = H[0 * 4 + u], h1 = H[1 * 4 + u],
                        h2 = H[2 * 4 + u], h3 = H[3 * 4 + u], hb = hq[u];
            float4 q;
            q.x = hb*bo.x + h0*r0.x + h1*r1.x + h2*r2.x + h3*r3.x;
            q.y = hb*bo.y + h0*r0.y + h1*r1.y + h2*r2.y + h3*r3.y;
            q.z = hb*bo.z + h0*r0.z + h1*r1.z + h2*r2.z + h3*r3.z;
            q.w = hb*bo.w + h0*r0.w + h1*r1.w + h2*r2.w + h3*r3.w;
            __stcs(&OMX[rbase[u] + c], q);
        }
    }
}

extern "C" void kernel_launch(void* const* d_in, const int* in_sizes, int n_in,
                              void* d_out, int out_size)
{
    const float* resid       = (const float*)d_in[0];
    const float* branch      = (const float*)d_in[1];
    const float* rmsw        = (const float*)d_in[2];
    const float* projW       = (const float*)d_in[3];
    const float* log_sigma   = (const float*)d_in[4];
    const float* pre_logits  = (const float*)d_in[5];
    const float* post_logits = (const float*)d_in[6];

    float* out_bi  = (float*)d_out;                                   // (B,T,D) first
    float* out_mix = (float*)d_out + (size_t)B_DIM * T_DIM * D_DIM;   // then (B*S,T,D)

    dim3 grid(B_DIM * T_DIM);
    dim3 block(256);
    ghc_kernel<<<grid, block>>>(resid, branch, rmsw, projW, log_sigma,
                                pre_logits, post_logits, out_bi, out_mix);
}